// round 16
// baseline (speedup 1.0000x reference)
#include <cuda_runtime.h>
#include <math.h>
#include <stdint.h>

// ---------------- problem constants ----------------
#define B_    32
#define S_    4096
#define HID_  5120
#define H_    16
#define DN_   128
#define DR_   64
#define DV_   128
#define QL_   1536
#define KL_   512
#define DK_   576
#define QKV_N (QL_ + KL_ + DR_)   // 2112
#define QB_N  (H_ * (DN_ + DR_))  // 3072
#define SCALE_ 0.07216878364870323f

#define SPLITS 16
#define CHUNK  (S_ / SPLITS)  // 256
#define TILE   16
#define NT     (CHUNK / TILE) // 16
#define KROW   580

// ---------------- f32x2 packed helpers (GEMM path) ----------------
__device__ __forceinline__ unsigned long long ffma2(unsigned long long a,
                                                    unsigned long long b,
                                                    unsigned long long c) {
    unsigned long long d;
    asm("fma.rn.f32x2 %0, %1, %2, %3;" : "=l"(d) : "l"(a), "l"(b), "l"(c));
    return d;
}
__device__ __forceinline__ void unpack2(unsigned long long a, float& lo, float& hi) {
    lo = __uint_as_float((unsigned)(a & 0xffffffffull));
    hi = __uint_as_float((unsigned)(a >> 32));
}

// ---------------- tf32 mma helpers ----------------
__device__ __forceinline__ float tf32r(float x) {
    uint32_t u;
    asm("cvt.rna.tf32.f32 %0, %1;" : "=r"(u) : "f"(x));
    return __uint_as_float(u);
}
__device__ __forceinline__ uint32_t fu(float x) { return __float_as_uint(x); }
__device__ __forceinline__ uint32_t tf32u(float x) {
    uint32_t u;
    asm("cvt.rna.tf32.f32 %0, %1;" : "=r"(u) : "f"(x));
    return u;
}
__device__ __forceinline__ void mma_tf32(float* d,
                                         uint32_t a0, uint32_t a1, uint32_t a2, uint32_t a3,
                                         uint32_t b0, uint32_t b1) {
    asm volatile(
        "mma.sync.aligned.m16n8k8.row.col.f32.tf32.tf32.f32 "
        "{%0,%1,%2,%3},{%4,%5,%6,%7},{%8,%9},{%0,%1,%2,%3};"
        : "+f"(d[0]), "+f"(d[1]), "+f"(d[2]), "+f"(d[3])
        : "r"(a0), "r"(a1), "r"(a2), "r"(a3), "r"(b0), "r"(b1));
}

// ---------------- cp.async helpers ----------------
__device__ __forceinline__ void cpa16(uint32_t dst, const void* src) {
    asm volatile("cp.async.cg.shared.global [%0], [%1], 16;\n" :: "r"(dst), "l"(src));
}
__device__ __forceinline__ void cp_commit() {
    asm volatile("cp.async.commit_group;\n");
}
template<int N> __device__ __forceinline__ void cp_wait() {
    asm volatile("cp.async.wait_group %0;\n" :: "n"(N));
}

// ---------------- device scratch ----------------
__device__ float g_p1[16][B_][QKV_N];
__device__ float g_qa_n[B_][QL_];
__device__ float g_latent_n[B_][KL_];
__device__ float g_kpe[B_][DR_];
__device__ float g_p2[8][B_][QB_N];
__device__ float g_q[B_][QB_N];
__device__ float g_qfinal[B_][H_][DK_];
__device__ float g_pm[B_][H_][SPLITS];
__device__ float g_pl[B_][H_][SPLITS];
__device__ float g_pctx[B_][SPLITS][H_][KL_];
__device__ float g_ctx[B_][H_][KL_];
__device__ float g_p4[4][B_][H_ * DV_];
__device__ float g_attn[B_][H_ * DV_];
__device__ float g_p3[8][B_][HID_];

// ---------------- skinny GEMM (f32x2, cp.async pipelined) ----------------
__global__ void __launch_bounds__(256) gemm32(
    const float* __restrict__ A, int lda, long sAh,
    const float* __restrict__ B, int ldb, long sBh,
    float* __restrict__ C, int ldc, long sCh, long cPart,
    int kchunk)
{
    __shared__ float As2[2][32 * 72];
    __shared__ float Bs[2][32 * 68];

    const int n0 = blockIdx.x * 64;
    const int k0 = blockIdx.y * kchunk;
    const int h  = blockIdx.z;
    A += (long)h * sAh;
    B += (long)h * sBh + n0;
    C += (long)h * sCh + (long)blockIdx.y * cPart + n0;

    const int t  = threadIdx.x;
    const int tn = t & 15;
    const int tm = t >> 4;
    const int arow = t >> 3, ac4 = (t & 7) * 4;
    const int br   = t >> 4, bc4 = (t & 15) * 4;

    const int iters = kchunk >> 5;

    unsigned long long c00 = 0, c01 = 0, c10 = 0, c11 = 0;

    float4 a_cur = *(const float4*)&A[(long)arow * lda + k0 + ac4];
    cpa16((uint32_t)__cvta_generic_to_shared(&Bs[0][br * 68 + bc4]),
          &B[(long)(k0 + br) * ldb + bc4]);
    cpa16((uint32_t)__cvta_generic_to_shared(&Bs[0][(br + 16) * 68 + bc4]),
          &B[(long)(k0 + br + 16) * ldb + bc4]);
    cp_commit();

    for (int it = 0; it < iters; it++) {
        const int p = it & 1;
        float4 a_nxt = a_cur;
        if (it + 1 < iters) {
            const int k = k0 + (it + 1) * 32;
            a_nxt = *(const float4*)&A[(long)arow * lda + k + ac4];
            cpa16((uint32_t)__cvta_generic_to_shared(&Bs[p ^ 1][br * 68 + bc4]),
                  &B[(long)(k + br) * ldb + bc4]);
            cpa16((uint32_t)__cvta_generic_to_shared(&Bs[p ^ 1][(br + 16) * 68 + bc4]),
                  &B[(long)(k + br + 16) * ldb + bc4]);
            cp_commit();
        }
        float* ad = &As2[p][arow * 72 + ac4 * 2];
        *(float2*)(ad + 0) = make_float2(a_cur.x, a_cur.x);
        *(float2*)(ad + 2) = make_float2(a_cur.y, a_cur.y);
        *(float2*)(ad + 4) = make_float2(a_cur.z, a_cur.z);
        *(float2*)(ad + 6) = make_float2(a_cur.w, a_cur.w);
        if (it + 1 < iters) cp_wait<1>(); else cp_wait<0>();
        __syncthreads();
        #pragma unroll
        for (int kk = 0; kk < 32; kk++) {
            unsigned long long a0 = *(const unsigned long long*)&As2[p][(tm * 2)     * 72 + kk * 2];
            unsigned long long a1 = *(const unsigned long long*)&As2[p][(tm * 2 + 1) * 72 + kk * 2];
            ulonglong2 b2 = *(const ulonglong2*)&Bs[p][kk * 68 + tn * 4];
            c00 = ffma2(a0, b2.x, c00); c01 = ffma2(a0, b2.y, c01);
            c10 = ffma2(a1, b2.x, c10); c11 = ffma2(a1, b2.y, c11);
        }
        __syncthreads();
        a_cur = a_nxt;
    }
    float4 o0, o1;
    unpack2(c00, o0.x, o0.y); unpack2(c01, o0.z, o0.w);
    unpack2(c10, o1.x, o1.y); unpack2(c11, o1.z, o1.w);
    *(float4*)&C[(long)(tm * 2)     * ldc + tn * 4] = o0;
    *(float4*)&C[(long)(tm * 2 + 1) * ldc + tn * 4] = o1;
}

// ---------------- split-K reduce ----------------
__global__ void reduceK(const float* __restrict__ parts, float* __restrict__ out,
                        int n, int nparts, long stride)
{
    for (int i = blockIdx.x * blockDim.x + threadIdx.x; i < n; i += gridDim.x * blockDim.x) {
        float s = 0.f;
        for (int j = 0; j < nparts; j++) s += parts[(long)j * stride + i];
        out[i] = s;
    }
}

// ---------------- fused reduce(p1) + rmsnorms + rope(k_pe) ----------------
__global__ void prep_kernel(const int* __restrict__ positions,
                            const float* __restrict__ q_w,
                            const float* __restrict__ kv_w)
{
    const int b = blockIdx.x, t = threadIdx.x;
    __shared__ float srow[QKV_N];
    __shared__ float red[256];

    for (int i = t; i < QKV_N; i += 256) {
        float s = 0.f;
        #pragma unroll
        for (int j = 0; j < 16; j++) s += g_p1[j][b][i];
        srow[i] = s;
    }
    __syncthreads();

    float ss = 0.f;
    for (int i = t; i < QL_; i += 256) { float v = srow[i]; ss += v * v; }
    red[t] = ss; __syncthreads();
    for (int o = 128; o > 0; o >>= 1) { if (t < o) red[t] += red[t + o]; __syncthreads(); }
    float r1 = rsqrtf(red[0] / (float)QL_ + 1e-6f);
    __syncthreads();
    for (int i = t; i < QL_; i += 256) g_qa_n[b][i] = srow[i] * r1 * q_w[i];

    ss = 0.f;
    for (int i = t; i < KL_; i += 256) { float v = srow[QL_ + i]; ss += v * v; }
    red[t] = ss; __syncthreads();
    for (int o = 128; o > 0; o >>= 1) { if (t < o) red[t] += red[t + o]; __syncthreads(); }
    float r2 = rsqrtf(red[0] / (float)KL_ + 1e-6f);
    __syncthreads();
    for (int i = t; i < KL_; i += 256) g_latent_n[b][i] = srow[QL_ + i] * r2 * kv_w[i];

    if (t < 32) {
        float x1 = srow[QL_ + KL_ + 2 * t];
        float x2 = srow[QL_ + KL_ + 2 * t + 1];
        float inv = (float)exp(-(double)(2 * t) / 64.0 * 9.210340371976184);
        float fr = (float)positions[b] * inv;
        float c = cosf(fr), s = sinf(fr);
        g_kpe[b][2 * t]     = x1 * c - x2 * s;
        g_kpe[b][2 * t + 1] = x2 * c + x1 * s;
    }
}

// ---------------- rope on q_pe ----------------
__global__ void rope_q(const int* __restrict__ positions)
{
    const int b = blockIdx.x, t = threadIdx.x;
    const float pos = (float)positions[b];
    for (int idx = t; idx < H_ * 32; idx += 256) {
        int h = idx >> 5, i = idx & 31;
        float x1 = g_q[b][h * 192 + 128 + 2 * i];
        float x2 = g_q[b][h * 192 + 128 + 2 * i + 1];
        float inv = (float)exp(-(double)(2 * i) / 64.0 * 9.210340371976184);
        float fr = pos * inv;
        float c = cosf(fr), s = sinf(fr);
        g_qfinal[b][h][512 + 2 * i]     = x1 * c - x2 * s;
        g_qfinal[b][h][512 + 2 * i + 1] = x2 * c + x1 * s;
    }
}

// ---------------- flash-decode attention v16: 256 threads, occ 2, tf32 mma ----------------
// grid (SPLITS, B) = 512 CTAs, 256 threads, TILE=16, NT=16.
// Scores: 8 warps = 8 k-slices, each computes both head-halves; Q frags in regs.
// ctx: each warp covers 64 cols (8 n-tiles), D[8][4] persistent fp32 frags.
// smem (floats):
//   sK0 [0,9280)  sK1 [9280,18560)     (16 x 580 each)
//   sSp [18560,21120)   8 ks x 16 s x 20
//   sPd [21120,21760)   16 s x 40 (P tf32)
//   sM  [21760,21776)  sL [21776,21792)  sCd [21792,21808)
#define ATTN_SMEM_FLOATS 21808

__global__ void __launch_bounds__(256, 2) attn_kernel(
    const float* __restrict__ cache_l,
    const float* __restrict__ cache_r)
{
    extern __shared__ float sm[];
    float* sK0 = sm;
    float* sK1 = sm + 9280;
    float* sSp = sm + 18560;
    float* sPd = sm + 21120;
    float* sM  = sm + 21760;
    float* sL  = sm + 21776;
    float* sCd = sm + 21792;

    const int split = blockIdx.x, b = blockIdx.y;
    const int t = threadIdx.x;
    const int lane = t & 31, w = t >> 5;        // 8 warps
    const int g = lane >> 2, j4 = lane & 3;
    const long bs = (long)b * S_;
    const float4* cl4 = (const float4*)cache_l;
    const float4* cr4 = (const float4*)cache_r;
    const int s0 = split * CHUNK;

    // staging coords: 16 rows x 16 chunks of 9 float4
    const int sr = t >> 4, scg = t & 15;
    const int ks = w;   // k-slice per warp

    // preload Q mma B-fragments in registers (tile-invariant): 36 regs
    uint32_t qf0[9][2], qf1[9][2];
    {
        const float* q0 = &g_qfinal[b][g][ks * 72];
        const float* q1 = &g_qfinal[b][g + 8][ks * 72];
        #pragma unroll
        for (int kt = 0; kt < 9; kt++) {
            qf0[kt][0] = tf32u(q0[kt * 8 + j4]);
            qf0[kt][1] = tf32u(q0[kt * 8 + j4 + 4]);
            qf1[kt][0] = tf32u(q1[kt * 8 + j4]);
            qf1[kt][1] = tf32u(q1[kt * 8 + j4 + 4]);
        }
    }
    if (t < 16) { sM[t] = -3.0e38f; sL[t] = 0.f; }

    // ctx accumulators: 8 n-tiles x 4 regs (64 cols per warp), persistent
    float D[8][4];
    #pragma unroll
    for (int n = 0; n < 8; n++) { D[n][0] = D[n][1] = D[n][2] = D[n][3] = 0.f; }

    // prologue: prefetch tile 0 into sK0 (16 rows x 144 float4; 9 per thread)
    {
        long row = bs + s0 + sr;
        const float4* ls = cl4 + row * 128;
        const float4* rs = cr4 + row * 16;
        uint32_t d = (uint32_t)__cvta_generic_to_shared(sK0 + sr * KROW);
        #pragma unroll
        for (int j = 0; j < 9; j++) {
            int idx = scg * 9 + j;
            const float4* src = (idx < 128) ? (ls + idx) : (rs + idx - 128);
            cpa16(d + idx * 16, src);
        }
        cp_commit();
    }

    for (int tile = 0; tile < NT; tile++) {
        float* kb = (tile & 1) ? sK1 : sK0;
        if (tile + 1 < NT) {
            float* kn = (tile & 1) ? sK0 : sK1;
            long row = bs + s0 + (tile + 1) * TILE + sr;
            const float4* ls = cl4 + row * 128;
            const float4* rs = cr4 + row * 16;
            uint32_t d = (uint32_t)__cvta_generic_to_shared(kn + sr * KROW);
            #pragma unroll
            for (int j = 0; j < 9; j++) {
                int idx = scg * 9 + j;
                const float4* src = (idx < 128) ? (ls + idx) : (rs + idx - 128);
                cpa16(d + idx * 16, src);
            }
            cp_commit();
            cp_wait<1>();
        } else {
            cp_wait<0>();
        }
        __syncthreads();

        // patch the freshly-computed last token (row 15, last tile of split 15)
        if (s0 + tile * TILE + TILE == S_) {
            if (t < 144) {
                float4 v = (t < 128) ? ((const float4*)&g_latent_n[b][0])[t]
                                     : ((const float4*)&g_kpe[b][0])[t - 128];
                *(float4*)&kb[15 * KROW + t * 4] = v;
            }
            __syncthreads();
        }

        // ---- scores via mma: warp = k-slice; both head halves ----
        {
            const float* kbp = kb + ks * 72;
            float d0[4] = {0.f, 0.f, 0.f, 0.f};
            float d1[4] = {0.f, 0.f, 0.f, 0.f};
            #pragma unroll
            for (int kt = 0; kt < 9; kt++) {
                const int dc = kt * 8 + j4;
                uint32_t a0 = tf32u(kbp[g * KROW + dc]);
                uint32_t a1 = tf32u(kbp[(g + 8) * KROW + dc]);
                uint32_t a2 = tf32u(kbp[g * KROW + dc + 4]);
                uint32_t a3 = tf32u(kbp[(g + 8) * KROW + dc + 4]);
                mma_tf32(d0, a0, a1, a2, a3, qf0[kt][0], qf0[kt][1]);
                mma_tf32(d1, a0, a1, a2, a3, qf1[kt][0], qf1[kt][1]);
            }
            // rows g, g+8 are s-positions; cols = heads
            float* sp = sSp + ks * 320 + g * 20 + 2 * j4;
            *(float2*)(sp)            = make_float2(d0[0], d0[1]);
            *(float2*)(sp + 8)        = make_float2(d1[0], d1[1]);
            *(float2*)(sp + 8 * 20)     = make_float2(d0[2], d0[3]);
            *(float2*)(sp + 8 * 20 + 8) = make_float2(d1[2], d1[3]);
        }
        __syncthreads();

        // ---- softmax: h = t>>4 (16 heads), s = t&15 ----
        {
            const int h = t >> 4, s = t & 15;
            float sc = 0.f;
            #pragma unroll
            for (int k = 0; k < 8; k++) sc += sSp[k * 320 + s * 20 + h];
            sc *= SCALE_;
            float m = sc;
            #pragma unroll
            for (int o = 8; o; o >>= 1) m = fmaxf(m, __shfl_xor_sync(0xffffffffu, m, o));
            float mold = sM[h];
            float mnew = fmaxf(mold, m);
            float p = __expf(sc - mnew);
            float l = p;
            #pragma unroll
            for (int o = 8; o; o >>= 1) l += __shfl_xor_sync(0xffffffffu, l, o);
            sPd[s * 40 + h] = tf32r(p);
            if (s == 0) {
                float corr = __expf(mold - mnew);
                sCd[h] = corr;
                sM[h] = mnew;
                sL[h] = sL[h] * corr + l;
            }
        }
        __syncthreads();

        // ---- ctx via mma: warp w -> cols [w*64, w*64+64); A rows = heads ----
        {
            const int c0 = w * 64;
            const float corr_lo = sCd[g], corr_hi = sCd[g + 8];
            #pragma unroll
            for (int n = 0; n < 8; n++) {
                D[n][0] *= corr_lo; D[n][1] *= corr_lo;
                D[n][2] *= corr_hi; D[n][3] *= corr_hi;
            }
            #pragma unroll
            for (int kt = 0; kt < 2; kt++) {
                const int k0i = kt * 8 + j4;
                uint32_t a0 = fu(sPd[k0i * 40 + g]);
                uint32_t a1 = fu(sPd[k0i * 40 + g + 8]);
                uint32_t a2 = fu(sPd[(k0i + 4) * 40 + g]);
                uint32_t a3 = fu(sPd[(k0i + 4) * 40 + g + 8]);
                #pragma unroll
                for (int n = 0; n < 8; n++) {
                    const int cc = c0 + n * 8 + g;
                    uint32_t v0 = tf32u(kb[k0i * KROW + cc]);
                    uint32_t v1 = tf32u(kb[(k0i + 4) * KROW + cc]);
                    mma_tf32(D[n], a0, a1, a2, a3, v0, v1);
                }
            }
        }
        __syncthreads();
    }

    // ---- write partials from D fragments ----
    {
        const int c0 = w * 64;
        float* op = &g_pctx[b][split][0][0];
        #pragma unroll
        for (int n = 0; n < 8; n++) {
            const int cc = c0 + n * 8 + 2 * j4;
            *(float2*)&op[g * 512 + cc]       = make_float2(D[n][0], D[n][1]);
            *(float2*)&op[(g + 8) * 512 + cc] = make_float2(D[n][2], D[n][3]);
        }
    }
    if (t < 16) {
        g_pm[b][t][split] = sM[t];
        g_pl[b][t][split] = sL[t];
    }
}

// ---------------- combine split partials ----------------
__global__ void attn_reduce()
{
    const int h = blockIdx.x, b = blockIdx.y;
    const int t = threadIdx.x;
    __shared__ float se[SPLITS];
    __shared__ float s_inv;
    if (t == 0) {
        float M = -1e30f;
        for (int i = 0; i < SPLITS; i++) M = fmaxf(M, g_pm[b][h][i]);
        float L = 0.f;
        for (int i = 0; i < SPLITS; i++) {
            float e = __expf(g_pm[b][h][i] - M);
            se[i] = e;
            L += g_pl[b][h][i] * e;
        }
        s_inv = 1.0f / L;
    }
    __syncthreads();
    float4 o = make_float4(0.f, 0.f, 0.f, 0.f);
    for (int i = 0; i < SPLITS; i++) {
        float e = se[i];
        float4 v = ((const float4*)&g_pctx[b][i][h][0])[t];
        o.x += e * v.x; o.y += e * v.y; o.z += e * v.z; o.w += e * v.w;
    }
    float inv = s_inv;
    o.x *= inv; o.y *= inv; o.z *= inv; o.w *= inv;
    ((float4*)&g_ctx[b][h][0])[t] = o;
}

// ---------------- host launcher ----------------
extern "C" void kernel_launch(void* const* d_in, const int* in_sizes, int n_in,
                              void* d_out, int out_size)
{
    (void)in_sizes; (void)n_in; (void)out_size;
    const float* hidden    = (const float*)d_in[0];
    const int*   positions = (const int*)  d_in[1];
    const float* cache_l   = (const float*)d_in[2];
    const float* cache_r   = (const float*)d_in[3];
    const float* w_qkv_a   = (const float*)d_in[4];
    const float* q_norm_w  = (const float*)d_in[5];
    const float* w_q_b     = (const float*)d_in[6];
    const float* kv_norm_w = (const float*)d_in[7];
    const float* w_kc      = (const float*)d_in[8];
    const float* w_vc      = (const float*)d_in[9];
    const float* w_o       = (const float*)d_in[10];
    float* out = (float*)d_out;

    float *p1, *qa_n, *p2, *q, *qf, *ctx, *p4, *attnb, *p3;
    cudaGetSymbolAddress((void**)&p1,    g_p1);
    cudaGetSymbolAddress((void**)&qa_n,  g_qa_n);
    cudaGetSymbolAddress((void**)&p2,    g_p2);
    cudaGetSymbolAddress((void**)&q,     g_q);
    cudaGetSymbolAddress((void**)&qf,    g_qfinal);
    cudaGetSymbolAddress((void**)&ctx,   g_ctx);
    cudaGetSymbolAddress((void**)&p4,    g_p4);
    cudaGetSymbolAddress((void**)&attnb, g_attn);
    cudaGetSymbolAddress((void**)&p3,    g_p3);

    const int ATTN_SMEM = ATTN_SMEM_FLOATS * 4;  // 87232 B -> 2 CTAs/SM
    cudaFuncSetAttribute(attn_kernel, cudaFuncAttributeMaxDynamicSharedMemorySize, ATTN_SMEM);

    // 1) qkv = hidden @ w_qkv_a   (split-K x16); reduction fused into prep
    gemm32<<<dim3(QKV_N / 64, 16, 1), 256>>>(hidden, HID_, 0, w_qkv_a, QKV_N, 0,
                                             p1, QKV_N, 0, 32L * QKV_N, HID_ / 16);

    // 2) fused reduce + rmsnorms + rope(k_pe)
    prep_kernel<<<B_, 256>>>(positions, q_norm_w, kv_norm_w);

    // 3) q = rmsnorm(q_a) @ w_q_b  (split-K x8)
    gemm32<<<dim3(QB_N / 64, 8, 1), 256>>>(qa_n, QL_, 0, w_q_b, QB_N, 0,
                                           p2, QB_N, 0, 32L * QB_N, QL_ / 8);
    reduceK<<<264, 256>>>(p2, q, B_ * QB_N, 8, 32L * QB_N);

    // 4) rope(q_pe) -> qfinal[...,512:576]
    rope_q<<<B_, 256>>>(positions);

    // 5) q_abs = q_nope @ w_kc[h] -> qfinal[...,0:512]
    gemm32<<<dim3(KL_ / 64, 1, H_), 256>>>(q, QB_N, 192, w_kc, KL_, (long)DN_ * KL_,
                                           qf, H_ * DK_, DK_, 0, DN_);

    // 6) flash-decode attention (tf32 mma, Q in regs, 256 thr / occ 2)
    attn_kernel<<<dim3(SPLITS, B_), 256, ATTN_SMEM>>>(cache_l, cache_r);
    attn_reduce<<<dim3(H_, B_), 128>>>();

    // 7) per-head value projection (split-K x4)
    gemm32<<<dim3(DV_ / 64, 4, H_), 256>>>(ctx, H_ * KL_, KL_, w_vc, DV_, (long)KL_ * DV_,
                                           p4, H_ * DV_, DV_, 32L * H_ * DV_, KL_ / 4);
    reduceK<<<264, 256>>>(p4, attnb, B_ * H_ * DV_, 4, 32L * H_ * DV_);

    // 8) out = attn @ w_o   (split-K x8)
    gemm32<<<dim3(HID_ / 64, 8, 1), 256>>>(attnb, H_ * DV_, 0, w_o, HID_, 0,
                                           p3, HID_, 0, 32L * HID_, (H_ * DV_) / 8);
    reduceK<<<264, 256>>>(p3, out, B_ * HID_, 8, 32L * HID_);
}

// round 17
// speedup vs baseline: 1.1766x; 1.1766x over previous
#include <cuda_runtime.h>
#include <math.h>
#include <stdint.h>

// ---------------- problem constants ----------------
#define B_    32
#define S_    4096
#define HID_  5120
#define H_    16
#define DN_   128
#define DR_   64
#define DV_   128
#define QL_   1536
#define KL_   512
#define DK_   576
#define QKV_N (QL_ + KL_ + DR_)   // 2112
#define QB_N  (H_ * (DN_ + DR_))  // 3072
#define SCALE_ 0.07216878364870323f

#define SPLITS 16
#define CHUNK  (S_ / SPLITS)  // 256
#define TILE   32
#define NT     (CHUNK / TILE) // 8
#define KROW   580

// ---------------- f32x2 packed helpers (GEMM path) ----------------
__device__ __forceinline__ unsigned long long ffma2(unsigned long long a,
                                                    unsigned long long b,
                                                    unsigned long long c) {
    unsigned long long d;
    asm("fma.rn.f32x2 %0, %1, %2, %3;" : "=l"(d) : "l"(a), "l"(b), "l"(c));
    return d;
}
__device__ __forceinline__ void unpack2(unsigned long long a, float& lo, float& hi) {
    lo = __uint_as_float((unsigned)(a & 0xffffffffull));
    hi = __uint_as_float((unsigned)(a >> 32));
}

// ---------------- tf32 mma helpers ----------------
__device__ __forceinline__ float tf32r(float x) {
    uint32_t u;
    asm("cvt.rna.tf32.f32 %0, %1;" : "=r"(u) : "f"(x));
    return __uint_as_float(u);
}
__device__ __forceinline__ uint32_t fu(float x) { return __float_as_uint(x); }
__device__ __forceinline__ uint32_t tf32u(float x) {
    uint32_t u;
    asm("cvt.rna.tf32.f32 %0, %1;" : "=r"(u) : "f"(x));
    return u;
}
__device__ __forceinline__ void mma_tf32(float* d,
                                         uint32_t a0, uint32_t a1, uint32_t a2, uint32_t a3,
                                         uint32_t b0, uint32_t b1) {
    asm volatile(
        "mma.sync.aligned.m16n8k8.row.col.f32.tf32.tf32.f32 "
        "{%0,%1,%2,%3},{%4,%5,%6,%7},{%8,%9},{%0,%1,%2,%3};"
        : "+f"(d[0]), "+f"(d[1]), "+f"(d[2]), "+f"(d[3])
        : "r"(a0), "r"(a1), "r"(a2), "r"(a3), "r"(b0), "r"(b1));
}

// ---------------- cp.async helpers ----------------
__device__ __forceinline__ void cpa16(uint32_t dst, const void* src) {
    asm volatile("cp.async.cg.shared.global [%0], [%1], 16;\n" :: "r"(dst), "l"(src));
}
__device__ __forceinline__ void cp_commit() {
    asm volatile("cp.async.commit_group;\n");
}
template<int N> __device__ __forceinline__ void cp_wait() {
    asm volatile("cp.async.wait_group %0;\n" :: "n"(N));
}

// ---------------- device scratch ----------------
__device__ float g_p1[32][B_][QKV_N];
__device__ float g_qa_n[B_][QL_];
__device__ float g_latent_n[B_][KL_];
__device__ float g_kpe[B_][DR_];
__device__ float g_p2[16][B_][QB_N];
__device__ float g_q[B_][QB_N];
__device__ float g_qfinal[B_][H_][DK_];
__device__ float g_pm[B_][H_][SPLITS];
__device__ float g_pl[B_][H_][SPLITS];
__device__ float g_pctx[B_][SPLITS][H_][KL_];
__device__ float g_ctx[B_][H_][KL_];
__device__ float g_p4[8][B_][H_ * DV_];
__device__ float g_attn[B_][H_ * DV_];
__device__ float g_p3[16][B_][HID_];

// ---------------- skinny GEMM (f32x2, cp.async pipelined) ----------------
__global__ void __launch_bounds__(256) gemm32(
    const float* __restrict__ A, int lda, long sAh,
    const float* __restrict__ B, int ldb, long sBh,
    float* __restrict__ C, int ldc, long sCh, long cPart,
    int kchunk)
{
    __shared__ float As2[2][32 * 72];
    __shared__ float Bs[2][32 * 68];

    const int n0 = blockIdx.x * 64;
    const int k0 = blockIdx.y * kchunk;
    const int h  = blockIdx.z;
    A += (long)h * sAh;
    B += (long)h * sBh + n0;
    C += (long)h * sCh + (long)blockIdx.y * cPart + n0;

    const int t  = threadIdx.x;
    const int tn = t & 15;
    const int tm = t >> 4;
    const int arow = t >> 3, ac4 = (t & 7) * 4;
    const int br   = t >> 4, bc4 = (t & 15) * 4;

    const int iters = kchunk >> 5;

    unsigned long long c00 = 0, c01 = 0, c10 = 0, c11 = 0;

    float4 a_cur = *(const float4*)&A[(long)arow * lda + k0 + ac4];
    cpa16((uint32_t)__cvta_generic_to_shared(&Bs[0][br * 68 + bc4]),
          &B[(long)(k0 + br) * ldb + bc4]);
    cpa16((uint32_t)__cvta_generic_to_shared(&Bs[0][(br + 16) * 68 + bc4]),
          &B[(long)(k0 + br + 16) * ldb + bc4]);
    cp_commit();

    for (int it = 0; it < iters; it++) {
        const int p = it & 1;
        float4 a_nxt = a_cur;
        if (it + 1 < iters) {
            const int k = k0 + (it + 1) * 32;
            a_nxt = *(const float4*)&A[(long)arow * lda + k + ac4];
            cpa16((uint32_t)__cvta_generic_to_shared(&Bs[p ^ 1][br * 68 + bc4]),
                  &B[(long)(k + br) * ldb + bc4]);
            cpa16((uint32_t)__cvta_generic_to_shared(&Bs[p ^ 1][(br + 16) * 68 + bc4]),
                  &B[(long)(k + br + 16) * ldb + bc4]);
            cp_commit();
        }
        float* ad = &As2[p][arow * 72 + ac4 * 2];
        *(float2*)(ad + 0) = make_float2(a_cur.x, a_cur.x);
        *(float2*)(ad + 2) = make_float2(a_cur.y, a_cur.y);
        *(float2*)(ad + 4) = make_float2(a_cur.z, a_cur.z);
        *(float2*)(ad + 6) = make_float2(a_cur.w, a_cur.w);
        if (it + 1 < iters) cp_wait<1>(); else cp_wait<0>();
        __syncthreads();
        #pragma unroll
        for (int kk = 0; kk < 32; kk++) {
            unsigned long long a0 = *(const unsigned long long*)&As2[p][(tm * 2)     * 72 + kk * 2];
            unsigned long long a1 = *(const unsigned long long*)&As2[p][(tm * 2 + 1) * 72 + kk * 2];
            ulonglong2 b2 = *(const ulonglong2*)&Bs[p][kk * 68 + tn * 4];
            c00 = ffma2(a0, b2.x, c00); c01 = ffma2(a0, b2.y, c01);
            c10 = ffma2(a1, b2.x, c10); c11 = ffma2(a1, b2.y, c11);
        }
        __syncthreads();
        a_cur = a_nxt;
    }
    float4 o0, o1;
    unpack2(c00, o0.x, o0.y); unpack2(c01, o0.z, o0.w);
    unpack2(c10, o1.x, o1.y); unpack2(c11, o1.z, o1.w);
    *(float4*)&C[(long)(tm * 2)     * ldc + tn * 4] = o0;
    *(float4*)&C[(long)(tm * 2 + 1) * ldc + tn * 4] = o1;
}

// ---------------- split-K reduce ----------------
__global__ void reduceK(const float* __restrict__ parts, float* __restrict__ out,
                        int n, int nparts, long stride)
{
    for (int i = blockIdx.x * blockDim.x + threadIdx.x; i < n; i += gridDim.x * blockDim.x) {
        float s = 0.f;
        for (int j = 0; j < nparts; j++) s += parts[(long)j * stride + i];
        out[i] = s;
    }
}

// ---------------- fused reduce(p1) + rmsnorms + rope(k_pe) ----------------
__global__ void prep_kernel(const int* __restrict__ positions,
                            const float* __restrict__ q_w,
                            const float* __restrict__ kv_w)
{
    const int b = blockIdx.x, t = threadIdx.x;
    __shared__ float srow[QKV_N];
    __shared__ float red[256];

    for (int i = t; i < QKV_N; i += 256) {
        float s = 0.f;
        #pragma unroll
        for (int j = 0; j < 32; j++) s += g_p1[j][b][i];
        srow[i] = s;
    }
    __syncthreads();

    float ss = 0.f;
    for (int i = t; i < QL_; i += 256) { float v = srow[i]; ss += v * v; }
    red[t] = ss; __syncthreads();
    for (int o = 128; o > 0; o >>= 1) { if (t < o) red[t] += red[t + o]; __syncthreads(); }
    float r1 = rsqrtf(red[0] / (float)QL_ + 1e-6f);
    __syncthreads();
    for (int i = t; i < QL_; i += 256) g_qa_n[b][i] = srow[i] * r1 * q_w[i];

    ss = 0.f;
    for (int i = t; i < KL_; i += 256) { float v = srow[QL_ + i]; ss += v * v; }
    red[t] = ss; __syncthreads();
    for (int o = 128; o > 0; o >>= 1) { if (t < o) red[t] += red[t + o]; __syncthreads(); }
    float r2 = rsqrtf(red[0] / (float)KL_ + 1e-6f);
    __syncthreads();
    for (int i = t; i < KL_; i += 256) g_latent_n[b][i] = srow[QL_ + i] * r2 * kv_w[i];

    if (t < 32) {
        float x1 = srow[QL_ + KL_ + 2 * t];
        float x2 = srow[QL_ + KL_ + 2 * t + 1];
        float inv = (float)exp(-(double)(2 * t) / 64.0 * 9.210340371976184);
        float fr = (float)positions[b] * inv;
        float c = cosf(fr), s = sinf(fr);
        g_kpe[b][2 * t]     = x1 * c - x2 * s;
        g_kpe[b][2 * t + 1] = x2 * c + x1 * s;
    }
}

// ---------------- rope on q_pe ----------------
__global__ void rope_q(const int* __restrict__ positions)
{
    const int b = blockIdx.x, t = threadIdx.x;
    const float pos = (float)positions[b];
    for (int idx = t; idx < H_ * 32; idx += 256) {
        int h = idx >> 5, i = idx & 31;
        float x1 = g_q[b][h * 192 + 128 + 2 * i];
        float x2 = g_q[b][h * 192 + 128 + 2 * i + 1];
        float inv = (float)exp(-(double)(2 * i) / 64.0 * 9.210340371976184);
        float fr = pos * inv;
        float c = cosf(fr), s = sinf(fr);
        g_qfinal[b][h][512 + 2 * i]     = x1 * c - x2 * s;
        g_qfinal[b][h][512 + 2 * i + 1] = x2 * c + x1 * s;
    }
}

// ---------------- flash-decode attention (R11): tf32 mma, Q in regs ----------------
// smem (floats):
//   sK0 [0,18560)  sK1 [18560,37120)     (32 x 580 each)
//   sSp [37120,42240)   8 ks x 32 s x 20
//   sPd [42240,43520)   32 s x 40 (P tf32)
//   sM  [43520,43536)  sL [43536,43552)  sCd [43552,43568)
#define ATTN_SMEM_FLOATS 43568

__global__ void __launch_bounds__(512, 1) attn_kernel(
    const float* __restrict__ cache_l,
    const float* __restrict__ cache_r)
{
    extern __shared__ float sm[];
    float* sK0 = sm;
    float* sK1 = sm + 18560;
    float* sSp = sm + 37120;
    float* sPd = sm + 42240;
    float* sM  = sm + 43520;
    float* sL  = sm + 43536;
    float* sCd = sm + 43552;

    const int split = blockIdx.x, b = blockIdx.y;
    const int t = threadIdx.x;
    const int lane = t & 31, w = t >> 5;
    const int g = lane >> 2, j4 = lane & 3;
    const long bs = (long)b * S_;
    const float4* cl4 = (const float4*)cache_l;
    const float4* cr4 = (const float4*)cache_r;
    const int s0 = split * CHUNK;

    const int sr = t >> 4, scg = t & 15;
    const int ms = (w & 1) * 16;
    const int ks = w >> 1;

    // preload Q mma B-fragments in registers (tile-invariant): 36 regs
    uint32_t qf0[9][2], qf1[9][2];
    {
        const float* q0 = &g_qfinal[b][g][ks * 72];
        const float* q1 = &g_qfinal[b][g + 8][ks * 72];
        #pragma unroll
        for (int kt = 0; kt < 9; kt++) {
            qf0[kt][0] = tf32u(q0[kt * 8 + j4]);
            qf0[kt][1] = tf32u(q0[kt * 8 + j4 + 4]);
            qf1[kt][0] = tf32u(q1[kt * 8 + j4]);
            qf1[kt][1] = tf32u(q1[kt * 8 + j4 + 4]);
        }
    }
    if (t < 16) { sM[t] = -3.0e38f; sL[t] = 0.f; }

    float D[4][4];
    #pragma unroll
    for (int n = 0; n < 4; n++) { D[n][0] = D[n][1] = D[n][2] = D[n][3] = 0.f; }

    // prologue: prefetch tile 0 into sK0
    {
        long row = bs + s0 + sr;
        const float4* ls = cl4 + row * 128;
        const float4* rs = cr4 + row * 16;
        uint32_t d = (uint32_t)__cvta_generic_to_shared(sK0 + sr * KROW + scg * 4);
        #pragma unroll
        for (int j = 0; j < 8; j++) cpa16(d + j * 256, ls + scg + j * 16);
        cpa16(d + 8 * 256, rs + scg);
        cp_commit();
    }

    for (int tile = 0; tile < NT; tile++) {
        float* kb = (tile & 1) ? sK1 : sK0;
        if (tile + 1 < NT) {
            float* kn = (tile & 1) ? sK0 : sK1;
            long row = bs + s0 + (tile + 1) * TILE + sr;
            const float4* ls = cl4 + row * 128;
            const float4* rs = cr4 + row * 16;
            uint32_t d = (uint32_t)__cvta_generic_to_shared(kn + sr * KROW + scg * 4);
            #pragma unroll
            for (int j = 0; j < 8; j++) cpa16(d + j * 256, ls + scg + j * 16);
            cpa16(d + 8 * 256, rs + scg);
            cp_commit();
            cp_wait<1>();
        } else {
            cp_wait<0>();
        }
        __syncthreads();

        if (s0 + tile * TILE + TILE == S_) {
            if (t < 144) {
                float4 v = (t < 128) ? ((const float4*)&g_latent_n[b][0])[t]
                                     : ((const float4*)&g_kpe[b][0])[t - 128];
                *(float4*)&kb[31 * KROW + t * 4] = v;
            }
            __syncthreads();
        }

        // ---- scores via mma ----
        {
            const float* kbp = kb + ms * KROW + ks * 72;
            float d0[4] = {0.f, 0.f, 0.f, 0.f};
            float d1[4] = {0.f, 0.f, 0.f, 0.f};
            #pragma unroll
            for (int kt = 0; kt < 9; kt++) {
                const int dc = kt * 8 + j4;
                uint32_t a0 = tf32u(kbp[g * KROW + dc]);
                uint32_t a1 = tf32u(kbp[(g + 8) * KROW + dc]);
                uint32_t a2 = tf32u(kbp[g * KROW + dc + 4]);
                uint32_t a3 = tf32u(kbp[(g + 8) * KROW + dc + 4]);
                mma_tf32(d0, a0, a1, a2, a3, qf0[kt][0], qf0[kt][1]);
                mma_tf32(d1, a0, a1, a2, a3, qf1[kt][0], qf1[kt][1]);
            }
            float* sp = sSp + ks * 640 + (ms + g) * 20 + 2 * j4;
            *(float2*)(sp)            = make_float2(d0[0], d0[1]);
            *(float2*)(sp + 8)        = make_float2(d1[0], d1[1]);
            *(float2*)(sp + 8 * 20)     = make_float2(d0[2], d0[3]);
            *(float2*)(sp + 8 * 20 + 8) = make_float2(d1[2], d1[3]);
        }
        __syncthreads();

        // ---- softmax ----
        {
            float sc = 0.f;
            #pragma unroll
            for (int k = 0; k < 8; k++) sc += sSp[k * 640 + lane * 20 + w];
            sc *= SCALE_;
            float m = sc;
            #pragma unroll
            for (int o = 16; o; o >>= 1) m = fmaxf(m, __shfl_xor_sync(0xffffffffu, m, o));
            float mold = sM[w];
            float mnew = fmaxf(mold, m);
            float p = __expf(sc - mnew);
            float l = p;
            #pragma unroll
            for (int o = 16; o; o >>= 1) l += __shfl_xor_sync(0xffffffffu, l, o);
            sPd[lane * 40 + w] = tf32r(p);
            if (lane == 0) {
                float corr = __expf(mold - mnew);
                sCd[w] = corr;
                sM[w] = mnew;
                sL[w] = sL[w] * corr + l;
            }
        }
        __syncthreads();

        // ---- ctx via mma ----
        {
            const int c0 = w * 32;
            const float corr_lo = sCd[g], corr_hi = sCd[g + 8];
            #pragma unroll
            for (int n = 0; n < 4; n++) {
                D[n][0] *= corr_lo; D[n][1] *= corr_lo;
                D[n][2] *= corr_hi; D[n][3] *= corr_hi;
            }
            #pragma unroll
            for (int kt = 0; kt < 4; kt++) {
                const int k0i = kt * 8 + j4;
                uint32_t a0 = fu(sPd[k0i * 40 + g]);
                uint32_t a1 = fu(sPd[k0i * 40 + g + 8]);
                uint32_t a2 = fu(sPd[(k0i + 4) * 40 + g]);
                uint32_t a3 = fu(sPd[(k0i + 4) * 40 + g + 8]);
                #pragma unroll
                for (int n = 0; n < 4; n++) {
                    const int cc = c0 + n * 8 + g;
                    uint32_t v0 = tf32u(kb[k0i * KROW + cc]);
                    uint32_t v1 = tf32u(kb[(k0i + 4) * KROW + cc]);
                    mma_tf32(D[n], a0, a1, a2, a3, v0, v1);
                }
            }
        }
        __syncthreads();
    }

    // ---- write partials ----
    {
        const int c0 = w * 32;
        float* op = &g_pctx[b][split][0][0];
        #pragma unroll
        for (int n = 0; n < 4; n++) {
            const int cc = c0 + n * 8 + 2 * j4;
            *(float2*)&op[g * 512 + cc]       = make_float2(D[n][0], D[n][1]);
            *(float2*)&op[(g + 8) * 512 + cc] = make_float2(D[n][2], D[n][3]);
        }
    }
    if (t < 16) {
        g_pm[b][t][split] = sM[t];
        g_pl[b][t][split] = sL[t];
    }
}

// ---------------- combine split partials ----------------
__global__ void attn_reduce()
{
    const int h = blockIdx.x, b = blockIdx.y;
    const int t = threadIdx.x;
    __shared__ float se[SPLITS];
    __shared__ float s_inv;
    if (t == 0) {
        float M = -1e30f;
        for (int i = 0; i < SPLITS; i++) M = fmaxf(M, g_pm[b][h][i]);
        float L = 0.f;
        for (int i = 0; i < SPLITS; i++) {
            float e = __expf(g_pm[b][h][i] - M);
            se[i] = e;
            L += g_pl[b][h][i] * e;
        }
        s_inv = 1.0f / L;
    }
    __syncthreads();
    float4 o = make_float4(0.f, 0.f, 0.f, 0.f);
    for (int i = 0; i < SPLITS; i++) {
        float e = se[i];
        float4 v = ((const float4*)&g_pctx[b][i][h][0])[t];
        o.x += e * v.x; o.y += e * v.y; o.z += e * v.z; o.w += e * v.w;
    }
    float inv = s_inv;
    o.x *= inv; o.y *= inv; o.z *= inv; o.w *= inv;
    ((float4*)&g_ctx[b][h][0])[t] = o;
}

// ---------------- host launcher ----------------
extern "C" void kernel_launch(void* const* d_in, const int* in_sizes, int n_in,
                              void* d_out, int out_size)
{
    (void)in_sizes; (void)n_in; (void)out_size;
    const float* hidden    = (const float*)d_in[0];
    const int*   positions = (const int*)  d_in[1];
    const float* cache_l   = (const float*)d_in[2];
    const float* cache_r   = (const float*)d_in[3];
    const float* w_qkv_a   = (const float*)d_in[4];
    const float* q_norm_w  = (const float*)d_in[5];
    const float* w_q_b     = (const float*)d_in[6];
    const float* kv_norm_w = (const float*)d_in[7];
    const float* w_kc      = (const float*)d_in[8];
    const float* w_vc      = (const float*)d_in[9];
    const float* w_o       = (const float*)d_in[10];
    float* out = (float*)d_out;

    float *p1, *qa_n, *p2, *q, *qf, *ctx, *p4, *attnb, *p3;
    cudaGetSymbolAddress((void**)&p1,    g_p1);
    cudaGetSymbolAddress((void**)&qa_n,  g_qa_n);
    cudaGetSymbolAddress((void**)&p2,    g_p2);
    cudaGetSymbolAddress((void**)&q,     g_q);
    cudaGetSymbolAddress((void**)&qf,    g_qfinal);
    cudaGetSymbolAddress((void**)&ctx,   g_ctx);
    cudaGetSymbolAddress((void**)&p4,    g_p4);
    cudaGetSymbolAddress((void**)&attnb, g_attn);
    cudaGetSymbolAddress((void**)&p3,    g_p3);

    const int ATTN_SMEM = ATTN_SMEM_FLOATS * 4;  // 174272 B
    cudaFuncSetAttribute(attn_kernel, cudaFuncAttributeMaxDynamicSharedMemorySize, ATTN_SMEM);

    // 1) qkv = hidden @ w_qkv_a   (split-K x32, 5 iters/CTA); reduce fused in prep
    gemm32<<<dim3(QKV_N / 64, 32, 1), 256>>>(hidden, HID_, 0, w_qkv_a, QKV_N, 0,
                                             p1, QKV_N, 0, 32L * QKV_N, HID_ / 32);

    // 2) fused reduce + rmsnorms + rope(k_pe)
    prep_kernel<<<B_, 256>>>(positions, q_norm_w, kv_norm_w);

    // 3) q = rmsnorm(q_a) @ w_q_b  (split-K x16, 3 iters/CTA)
    gemm32<<<dim3(QB_N / 64, 16, 1), 256>>>(qa_n, QL_, 0, w_q_b, QB_N, 0,
                                            p2, QB_N, 0, 32L * QB_N, QL_ / 16);
    reduceK<<<264, 256>>>(p2, q, B_ * QB_N, 16, 32L * QB_N);

    // 4) rope(q_pe) -> qfinal[...,512:576]
    rope_q<<<B_, 256>>>(positions);

    // 5) q_abs = q_nope @ w_kc[h] -> qfinal[...,0:512]
    gemm32<<<dim3(KL_ / 64, 1, H_), 256>>>(q, QB_N, 192, w_kc, KL_, (long)DN_ * KL_,
                                           qf, H_ * DK_, DK_, 0, DN_);

    // 6) flash-decode attention (tf32 mma, Q in regs)
    attn_kernel<<<dim3(SPLITS, B_), 512, ATTN_SMEM>>>(cache_l, cache_r);
    attn_reduce<<<dim3(H_, B_), 128>>>();

    // 7) per-head value projection (split-K x8, 2 iters/CTA, grid 256)
    gemm32<<<dim3(DV_ / 64, 8, H_), 256>>>(ctx, H_ * KL_, KL_, w_vc, DV_, (long)KL_ * DV_,
                                           p4, H_ * DV_, DV_, 32L * H_ * DV_, KL_ / 8);
    reduceK<<<264, 256>>>(p4, attnb, B_ * H_ * DV_, 8, 32L * H_ * DV_);

    // 8) out = attn @ w_o   (split-K x16, 4 iters/CTA)
    gemm32<<<dim3(HID_ / 64, 16, 1), 256>>>(attnb, H_ * DV_, 0, w_o, HID_, 0,
                                            p3, HID_, 0, 32L * HID_, (H_ * DV_) / 16);
    reduceK<<<264, 256>>>(p3, out, B_ * HID_, 16, 32L * HID_);
}